// round 14
// baseline (speedup 1.0000x reference)
// R13: BKE=128 (32 chunks, half the barriers/primes), 2-stage ring,
// interleaved cp groups. 256 threads, CTA 128x256, warp tile 64x64.
#include <cuda_runtime.h>
#include <cuda_bf16.h>
#include <cstdint>
#include <cstddef>

#define N_TOK 8192
#define D_IN  4096
#define D_OUT 4096

__device__ __align__(16) __nv_bfloat16 g_Xb[(size_t)N_TOK * D_IN];   // 64 MB
__device__ __align__(16) __nv_bfloat16 g_Wb[(size_t)D_OUT * D_IN];   // 32 MB
__device__ unsigned g_absmax_u;

// ---------------- helpers ---------------------------------------------------
__device__ __forceinline__ uint32_t smem_u32(const void* p) {
    uint32_t a;
    asm("{ .reg .u64 t; cvta.to.shared.u64 t, %1; cvt.u32.u64 %0, t; }"
        : "=r"(a) : "l"(p));
    return a;
}

__device__ __forceinline__ void cp16(uint32_t dst, const void* src) {
    asm volatile("cp.async.cg.shared.global [%0], [%1], 16;" :: "r"(dst), "l"(src));
}

__device__ __forceinline__ void hmma16816(float* c, const uint32_t* a, const uint32_t* b) {
    asm volatile(
        "mma.sync.aligned.m16n8k16.row.col.f32.bf16.bf16.f32 "
        "{%0,%1,%2,%3}, {%4,%5,%6,%7}, {%8,%9}, {%0,%1,%2,%3};"
        : "+f"(c[0]), "+f"(c[1]), "+f"(c[2]), "+f"(c[3])
        : "r"(a[0]), "r"(a[1]), "r"(a[2]), "r"(a[3]), "r"(b[0]), "r"(b[1]));
}

__device__ __forceinline__ void ldm_x4(uint32_t* r, uint32_t addr) {
    asm volatile(
        "ldmatrix.sync.aligned.m8n8.x4.shared.b16 {%0,%1,%2,%3}, [%4];"
        : "=r"(r[0]), "=r"(r[1]), "=r"(r[2]), "=r"(r[3]) : "r"(addr));
}

// ---------------- pre-kernels ----------------------------------------------
__global__ void init_kernel() { g_absmax_u = 0u; }

__global__ void absmax_kernel(const float4* __restrict__ x, int n4) {
    float m = 0.f;
    for (int i = blockIdx.x * blockDim.x + threadIdx.x; i < n4;
         i += gridDim.x * blockDim.x) {
        float4 v = x[i];
        m = fmaxf(m, fmaxf(fmaxf(fabsf(v.x), fabsf(v.y)),
                           fmaxf(fabsf(v.z), fabsf(v.w))));
    }
#pragma unroll
    for (int o = 16; o > 0; o >>= 1)
        m = fmaxf(m, __shfl_xor_sync(0xffffffffu, m, o));
    __shared__ float red[8];
    if ((threadIdx.x & 31) == 0) red[threadIdx.x >> 5] = m;
    __syncthreads();
    if (threadIdx.x == 0) {
        float v = red[0];
#pragma unroll
        for (int i = 1; i < 8; ++i) v = fmaxf(v, red[i]);
        atomicMax(&g_absmax_u, __float_as_uint(v));   // values >= 0: bit-monotone
    }
}

__global__ void quant_kernel(const float4* __restrict__ x, int n4) {
    float am = __uint_as_float(g_absmax_u);
    float s = __fdiv_rn(am, 127.0f);            // exact IEEE div, matches reference
    if (s == 0.f) s = 1.0f;
    for (int i = blockIdx.x * blockDim.x + threadIdx.x; i < n4;
         i += gridDim.x * blockDim.x) {
        float4 v = x[i];
        float a0 = fminf(fmaxf(rintf(__fdiv_rn(v.x, s)), -128.f), 127.f);
        float a1 = fminf(fmaxf(rintf(__fdiv_rn(v.y, s)), -128.f), 127.f);
        float a2 = fminf(fmaxf(rintf(__fdiv_rn(v.z, s)), -128.f), 127.f);
        float a3 = fminf(fmaxf(rintf(__fdiv_rn(v.w, s)), -128.f), 127.f);
        __nv_bfloat162 h0 = __floats2bfloat162_rn(a0, a1);
        __nv_bfloat162 h1 = __floats2bfloat162_rn(a2, a3);
        uint2 u;
        u.x = *reinterpret_cast<uint32_t*>(&h0);
        u.y = *reinterpret_cast<uint32_t*>(&h1);
        reinterpret_cast<uint2*>(g_Xb)[i] = u;
    }
}

__global__ void wconv_kernel(const int4* __restrict__ w, int n4) {
    for (int i = blockIdx.x * blockDim.x + threadIdx.x; i < n4;
         i += gridDim.x * blockDim.x) {
        int4 v = w[i];   // values in {-1, 0, 1}
        __nv_bfloat162 h0 = __floats2bfloat162_rn((float)v.x, (float)v.y);
        __nv_bfloat162 h1 = __floats2bfloat162_rn((float)v.z, (float)v.w);
        uint2 u;
        u.x = *reinterpret_cast<uint32_t*>(&h0);
        u.y = *reinterpret_cast<uint32_t*>(&h1);
        reinterpret_cast<uint2*>(g_Wb)[i] = u;
    }
}

// ---------------- bf16 GEMM: C[8192,4096] = Xb @ Wb^T -----------------------
#define BM 128
#define BN 256
#define BKE 128                           // K elems per chunk
#define BKB (BKE * 2)                     // 256 bytes per row per chunk
#define LDS_ROW 272                       // 256B data + 16B pad (same bank geom as 144)
#define A_STAGE (BM * LDS_ROW)            // 34816
#define B_STAGE (BN * LDS_ROW)            // 69632
#define STAGE_BYTES (A_STAGE + B_STAGE)   // 104448
#define STAGES 2
#define BIAS_OFF (STAGES * STAGE_BYTES)   // 208896
#define SMEM_TOTAL (BIAS_OFF + BN * 4)    // 209920
#define NTHREADS 256

// one cp.async group: 256 ops, 1/thread. G in [0,24): G<8 -> A, else B.
template <int G>
__device__ __forceinline__ void cp_group(uint32_t fas, const char* agf,
                                         const char* bgf, int tid) {
    if (G < 8) {
        int idx = G * NTHREADS + tid;            // 0..2047 -> A (128 rows x 16)
        int row = idx >> 4, cc = idx & 15;
        cp16(fas + row * LDS_ROW + cc * 16,
             agf + (size_t)row * (D_IN * 2) + cc * 16);
    } else {
        int j = (G - 8) * NTHREADS + tid;        // 0..4095 -> B (256 rows x 16)
        int row = j >> 4, cc = j & 15;
        cp16(fas + A_STAGE + row * LDS_ROW + cc * 16,
             bgf + (size_t)row * (D_IN * 2) + cc * 16);
    }
}

__device__ __forceinline__ void fill_full(uint32_t fas, const char* agf,
                                          const char* bgf, int tid) {
    cp_group<0>(fas, agf, bgf, tid);   cp_group<1>(fas, agf, bgf, tid);
    cp_group<2>(fas, agf, bgf, tid);   cp_group<3>(fas, agf, bgf, tid);
    cp_group<4>(fas, agf, bgf, tid);   cp_group<5>(fas, agf, bgf, tid);
    cp_group<6>(fas, agf, bgf, tid);   cp_group<7>(fas, agf, bgf, tid);
    cp_group<8>(fas, agf, bgf, tid);   cp_group<9>(fas, agf, bgf, tid);
    cp_group<10>(fas, agf, bgf, tid);  cp_group<11>(fas, agf, bgf, tid);
    cp_group<12>(fas, agf, bgf, tid);  cp_group<13>(fas, agf, bgf, tid);
    cp_group<14>(fas, agf, bgf, tid);  cp_group<15>(fas, agf, bgf, tid);
    cp_group<16>(fas, agf, bgf, tid);  cp_group<17>(fas, agf, bgf, tid);
    cp_group<18>(fas, agf, bgf, tid);  cp_group<19>(fas, agf, bgf, tid);
    cp_group<20>(fas, agf, bgf, tid);  cp_group<21>(fas, agf, bgf, tid);
    cp_group<22>(fas, agf, bgf, tid);  cp_group<23>(fas, agf, bgf, tid);
    asm volatile("cp.async.commit_group;" ::: "memory");
}

__device__ __forceinline__ void load_frags(uint32_t stg, uint32_t aAddrBase,
                                           uint32_t bAddrBase, int ks,
                                           uint32_t a[4][4], uint32_t b[8][2]) {
#pragma unroll
    for (int mt = 0; mt < 4; ++mt)
        ldm_x4(a[mt], stg + aAddrBase + mt * (16 * LDS_ROW) + ks * 32);
#pragma unroll
    for (int ntp = 0; ntp < 4; ++ntp) {
        uint32_t r[4];
        ldm_x4(r, stg + bAddrBase + ntp * (16 * LDS_ROW) + ks * 32);
        b[ntp * 2 + 0][0] = r[0];
        b[ntp * 2 + 0][1] = r[1];
        b[ntp * 2 + 1][0] = r[2];
        b[ntp * 2 + 1][1] = r[3];
    }
}

__global__ void __launch_bounds__(NTHREADS, 1)
gemm_hmma(const float* __restrict__ bias, const float* __restrict__ wscale,
          float* __restrict__ out) {
    extern __shared__ char smem[];
    const uint32_t sbase = smem_u32(smem);
    const int tid = threadIdx.x;
    const int wid = tid >> 5, lane = tid & 31;
    const int g = lane >> 2, t = lane & 3;
    const int wm = wid & 1, wn = wid >> 1;           // 2 warps in M, 4 in N
    const int m0 = blockIdx.y * BM, n0 = blockIdx.x * BN;

    const char* Ag = (const char*)g_Xb + (size_t)m0 * (D_IN * 2);
    const char* Bg = (const char*)g_Wb + (size_t)n0 * (D_IN * 2);

    if (tid < BN) {
        float bv = bias[n0 + tid];
        *reinterpret_cast<float*>(smem + BIAS_OFF + tid * 4) = bv;
    }

    const uint32_t aAddrBase =
        (uint32_t)((wm * 64 + (lane & 15)) * LDS_ROW + ((lane >> 4) * 16));
    const uint32_t bAddrBase =
        (uint32_t)(A_STAGE +
                   (wn * 64 + (lane & 7) + ((lane >> 4) * 8)) * LDS_ROW +
                   (((lane >> 3) & 1) * 16));

    float acc[4][8][4];
#pragma unroll
    for (int mt = 0; mt < 4; ++mt)
#pragma unroll
        for (int nt = 0; nt < 8; ++nt)
#pragma unroll
            for (int i = 0; i < 4; ++i) acc[mt][nt][i] = 0.f;

    // prologue: fill stage 0 (chunk 0)
    fill_full(sbase, Ag, Bg, tid);

    uint32_t abuf[2][4][4], bbuf[2][8][2];

    const int NCHUNK = D_IN / BKE;   // 32
    for (int c = 0; c < NCHUNK; ++c) {
        asm volatile("cp.async.wait_group 0;" ::: "memory");
        __syncthreads();

        const uint32_t stg = sbase + (c & 1) * STAGE_BYTES;
        const bool fill = (c + 1 < NCHUNK);
        const uint32_t fas = sbase + ((c + 1) & 1) * STAGE_BYTES;
        const char* agf = Ag + (size_t)(c + 1) * BKB;
        const char* bgf = Bg + (size_t)(c + 1) * BKB;

        load_frags(stg, aAddrBase, bAddrBase, 0, abuf[0], bbuf[0]);
#pragma unroll
        for (int ks = 0; ks < 8; ++ks) {
            const int cur = ks & 1;
            if (ks < 7)
                load_frags(stg, aAddrBase, bAddrBase, ks + 1,
                           abuf[1 - cur], bbuf[1 - cur]);
            if (fill) {   // 3 cp groups per ks, hidden under the 32 HMMAs below
                switch (ks) {
                    case 0: cp_group<0>(fas, agf, bgf, tid);
                            cp_group<8>(fas, agf, bgf, tid);
                            cp_group<9>(fas, agf, bgf, tid);  break;
                    case 1: cp_group<1>(fas, agf, bgf, tid);
                            cp_group<10>(fas, agf, bgf, tid);
                            cp_group<11>(fas, agf, bgf, tid); break;
                    case 2: cp_group<2>(fas, agf, bgf, tid);
                            cp_group<12>(fas, agf, bgf, tid);
                            cp_group<13>(fas, agf, bgf, tid); break;
                    case 3: cp_group<3>(fas, agf, bgf, tid);
                            cp_group<14>(fas, agf, bgf, tid);
                            cp_group<15>(fas, agf, bgf, tid); break;
                    case 4: cp_group<4>(fas, agf, bgf, tid);
                            cp_group<16>(fas, agf, bgf, tid);
                            cp_group<17>(fas, agf, bgf, tid); break;
                    case 5: cp_group<5>(fas, agf, bgf, tid);
                            cp_group<18>(fas, agf, bgf, tid);
                            cp_group<19>(fas, agf, bgf, tid); break;
                    case 6: cp_group<6>(fas, agf, bgf, tid);
                            cp_group<20>(fas, agf, bgf, tid);
                            cp_group<21>(fas, agf, bgf, tid); break;
                    case 7: cp_group<7>(fas, agf, bgf, tid);
                            cp_group<22>(fas, agf, bgf, tid);
                            cp_group<23>(fas, agf, bgf, tid); break;
                }
            }
#pragma unroll
            for (int mt = 0; mt < 4; ++mt)
#pragma unroll
                for (int nt = 0; nt < 8; ++nt)
                    hmma16816(acc[mt][nt], abuf[cur][mt], bbuf[cur][nt]);
        }
        if (fill)
            asm volatile("cp.async.commit_group;" ::: "memory");
    }

    // epilogue: out = acc * (weight_scale * scale) + bias
    float am = __uint_as_float(g_absmax_u);
    float sc = __fdiv_rn(am, 127.0f);
    if (sc == 0.f) sc = 1.0f;
    float alpha = (*wscale) * sc;

    const float* bsh = reinterpret_cast<const float*>(smem + BIAS_OFF);
#pragma unroll
    for (int mt = 0; mt < 4; ++mt) {
#pragma unroll
        for (int nt = 0; nt < 8; ++nt) {
            int row = m0 + wm * 64 + mt * 16 + g;
            int lcol = wn * 64 + nt * 8 + t * 2;
            float b0 = bsh[lcol];
            float b1 = bsh[lcol + 1];
            float2 v0, v1;
            v0.x = acc[mt][nt][0] * alpha + b0;
            v0.y = acc[mt][nt][1] * alpha + b1;
            v1.x = acc[mt][nt][2] * alpha + b0;
            v1.y = acc[mt][nt][3] * alpha + b1;
            *reinterpret_cast<float2*>(out + (size_t)row * D_OUT + n0 + lcol) = v0;
            *reinterpret_cast<float2*>(out + (size_t)(row + 8) * D_OUT + n0 + lcol) = v1;
        }
    }
}

// ---------------- launcher --------------------------------------------------
extern "C" void kernel_launch(void* const* d_in, const int* in_sizes, int n_in,
                              void* d_out, int out_size) {
    const float* x    = (const float*)d_in[0];
    const int*   w    = (const int*)d_in[1];
    const float* ws   = (const float*)d_in[2];
    const float* bias = (const float*)d_in[3];
    float* out = (float*)d_out;

    cudaFuncSetAttribute(gemm_hmma, cudaFuncAttributeMaxDynamicSharedMemorySize,
                         SMEM_TOTAL);

    init_kernel<<<1, 1>>>();
    absmax_kernel<<<1024, 256>>>((const float4*)x, (N_TOK * D_IN) / 4);
    quant_kernel<<<2048, 256>>>((const float4*)x, (N_TOK * D_IN) / 4);
    wconv_kernel<<<1024, 256>>>((const int4*)w, (D_OUT * D_IN) / 4);

    dim3 grid(D_OUT / BN, N_TOK / BM);
    gemm_hmma<<<grid, NTHREADS, SMEM_TOTAL>>>(bias, ws, out);
}

// round 15
// speedup vs baseline: 1.6081x; 1.6081x over previous
// R15: R12 structure (known-good 666us) + 4-stage ring / wait_group 2
// for 2 chunks of load-latency slack. 256 thr, CTA 128x256, BKE=64.
#include <cuda_runtime.h>
#include <cuda_bf16.h>
#include <cstdint>
#include <cstddef>

#define N_TOK 8192
#define D_IN  4096
#define D_OUT 4096

__device__ __align__(16) __nv_bfloat16 g_Xb[(size_t)N_TOK * D_IN];   // 64 MB
__device__ __align__(16) __nv_bfloat16 g_Wb[(size_t)D_OUT * D_IN];   // 32 MB
__device__ unsigned g_absmax_u;

// ---------------- helpers ---------------------------------------------------
__device__ __forceinline__ uint32_t smem_u32(const void* p) {
    uint32_t a;
    asm("{ .reg .u64 t; cvta.to.shared.u64 t, %1; cvt.u32.u64 %0, t; }"
        : "=r"(a) : "l"(p));
    return a;
}

__device__ __forceinline__ void cp16(uint32_t dst, const void* src) {
    asm volatile("cp.async.cg.shared.global [%0], [%1], 16;" :: "r"(dst), "l"(src));
}

__device__ __forceinline__ void hmma16816(float* c, const uint32_t* a, const uint32_t* b) {
    asm volatile(
        "mma.sync.aligned.m16n8k16.row.col.f32.bf16.bf16.f32 "
        "{%0,%1,%2,%3}, {%4,%5,%6,%7}, {%8,%9}, {%0,%1,%2,%3};"
        : "+f"(c[0]), "+f"(c[1]), "+f"(c[2]), "+f"(c[3])
        : "r"(a[0]), "r"(a[1]), "r"(a[2]), "r"(a[3]), "r"(b[0]), "r"(b[1]));
}

__device__ __forceinline__ void ldm_x4(uint32_t* r, uint32_t addr) {
    asm volatile(
        "ldmatrix.sync.aligned.m8n8.x4.shared.b16 {%0,%1,%2,%3}, [%4];"
        : "=r"(r[0]), "=r"(r[1]), "=r"(r[2]), "=r"(r[3]) : "r"(addr));
}

// ---------------- pre-kernels ----------------------------------------------
__global__ void init_kernel() { g_absmax_u = 0u; }

__global__ void absmax_kernel(const float4* __restrict__ x, int n4) {
    float m = 0.f;
    for (int i = blockIdx.x * blockDim.x + threadIdx.x; i < n4;
         i += gridDim.x * blockDim.x) {
        float4 v = x[i];
        m = fmaxf(m, fmaxf(fmaxf(fabsf(v.x), fabsf(v.y)),
                           fmaxf(fabsf(v.z), fabsf(v.w))));
    }
#pragma unroll
    for (int o = 16; o > 0; o >>= 1)
        m = fmaxf(m, __shfl_xor_sync(0xffffffffu, m, o));
    __shared__ float red[8];
    if ((threadIdx.x & 31) == 0) red[threadIdx.x >> 5] = m;
    __syncthreads();
    if (threadIdx.x == 0) {
        float v = red[0];
#pragma unroll
        for (int i = 1; i < 8; ++i) v = fmaxf(v, red[i]);
        atomicMax(&g_absmax_u, __float_as_uint(v));   // values >= 0: bit-monotone
    }
}

__global__ void quant_kernel(const float4* __restrict__ x, int n4) {
    float am = __uint_as_float(g_absmax_u);
    float s = __fdiv_rn(am, 127.0f);            // exact IEEE div, matches reference
    if (s == 0.f) s = 1.0f;
    for (int i = blockIdx.x * blockDim.x + threadIdx.x; i < n4;
         i += gridDim.x * blockDim.x) {
        float4 v = x[i];
        float a0 = fminf(fmaxf(rintf(__fdiv_rn(v.x, s)), -128.f), 127.f);
        float a1 = fminf(fmaxf(rintf(__fdiv_rn(v.y, s)), -128.f), 127.f);
        float a2 = fminf(fmaxf(rintf(__fdiv_rn(v.z, s)), -128.f), 127.f);
        float a3 = fminf(fmaxf(rintf(__fdiv_rn(v.w, s)), -128.f), 127.f);
        __nv_bfloat162 h0 = __floats2bfloat162_rn(a0, a1);
        __nv_bfloat162 h1 = __floats2bfloat162_rn(a2, a3);
        uint2 u;
        u.x = *reinterpret_cast<uint32_t*>(&h0);
        u.y = *reinterpret_cast<uint32_t*>(&h1);
        reinterpret_cast<uint2*>(g_Xb)[i] = u;
    }
}

__global__ void wconv_kernel(const int4* __restrict__ w, int n4) {
    for (int i = blockIdx.x * blockDim.x + threadIdx.x; i < n4;
         i += gridDim.x * blockDim.x) {
        int4 v = w[i];   // values in {-1, 0, 1}
        __nv_bfloat162 h0 = __floats2bfloat162_rn((float)v.x, (float)v.y);
        __nv_bfloat162 h1 = __floats2bfloat162_rn((float)v.z, (float)v.w);
        uint2 u;
        u.x = *reinterpret_cast<uint32_t*>(&h0);
        u.y = *reinterpret_cast<uint32_t*>(&h1);
        reinterpret_cast<uint2*>(g_Wb)[i] = u;
    }
}

// ---------------- bf16 GEMM: C[8192,4096] = Xb @ Wb^T -----------------------
#define BM 128
#define BN 256
#define BKE 64
#define BKB (BKE * 2)                     // 128 bytes per row per chunk
#define LDS_ROW 144                       // 128B data + 16B pad
#define A_STAGE (BM * LDS_ROW)            // 18432
#define B_STAGE (BN * LDS_ROW)            // 36864
#define STAGE_BYTES (A_STAGE + B_STAGE)   // 55296
#define STAGES 4
#define BIAS_OFF (STAGES * STAGE_BYTES)   // 221184
#define SMEM_TOTAL (BIAS_OFF + BN * 4)    // 222208
#define NTHREADS 256

// one cp.async group: 256 ops, 1/thread. G in [0,12): G<4 -> A, else B.
template <int G>
__device__ __forceinline__ void cp_group(uint32_t fas, const char* agf,
                                         const char* bgf, int tid) {
    if (G < 4) {
        int idx = G * NTHREADS + tid;            // 0..1023 -> A
        int row = idx >> 3, cc = idx & 7;
        cp16(fas + row * LDS_ROW + cc * 16,
             agf + (size_t)row * (D_IN * 2) + cc * 16);
    } else {
        int j = (G - 4) * NTHREADS + tid;        // 0..2047 -> B
        int row = j >> 3, cc = j & 7;
        cp16(fas + A_STAGE + row * LDS_ROW + cc * 16,
             bgf + (size_t)row * (D_IN * 2) + cc * 16);
    }
}

__device__ __forceinline__ void fill_full(uint32_t fas, const char* agf,
                                          const char* bgf, int tid) {
    cp_group<0>(fas, agf, bgf, tid);  cp_group<1>(fas, agf, bgf, tid);
    cp_group<2>(fas, agf, bgf, tid);  cp_group<3>(fas, agf, bgf, tid);
    cp_group<4>(fas, agf, bgf, tid);  cp_group<5>(fas, agf, bgf, tid);
    cp_group<6>(fas, agf, bgf, tid);  cp_group<7>(fas, agf, bgf, tid);
    cp_group<8>(fas, agf, bgf, tid);  cp_group<9>(fas, agf, bgf, tid);
    cp_group<10>(fas, agf, bgf, tid); cp_group<11>(fas, agf, bgf, tid);
    asm volatile("cp.async.commit_group;" ::: "memory");
}

__device__ __forceinline__ void load_frags(uint32_t stg, uint32_t aAddrBase,
                                           uint32_t bAddrBase, int ks,
                                           uint32_t a[4][4], uint32_t b[8][2]) {
#pragma unroll
    for (int mt = 0; mt < 4; ++mt)
        ldm_x4(a[mt], stg + aAddrBase + mt * (16 * LDS_ROW) + ks * 32);
#pragma unroll
    for (int ntp = 0; ntp < 4; ++ntp) {
        uint32_t r[4];
        ldm_x4(r, stg + bAddrBase + ntp * (16 * LDS_ROW) + ks * 32);
        b[ntp * 2 + 0][0] = r[0];
        b[ntp * 2 + 0][1] = r[1];
        b[ntp * 2 + 1][0] = r[2];
        b[ntp * 2 + 1][1] = r[3];
    }
}

__global__ void __launch_bounds__(NTHREADS, 1)
gemm_hmma(const float* __restrict__ bias, const float* __restrict__ wscale,
          float* __restrict__ out) {
    extern __shared__ char smem[];
    const uint32_t sbase = smem_u32(smem);
    const int tid = threadIdx.x;
    const int wid = tid >> 5, lane = tid & 31;
    const int g = lane >> 2, t = lane & 3;
    const int wm = wid & 1, wn = wid >> 1;           // 2 warps in M, 4 in N
    const int m0 = blockIdx.y * BM, n0 = blockIdx.x * BN;

    const char* Ag = (const char*)g_Xb + (size_t)m0 * (D_IN * 2);
    const char* Bg = (const char*)g_Wb + (size_t)n0 * (D_IN * 2);

    if (tid < BN) {
        float bv = bias[n0 + tid];
        *reinterpret_cast<float*>(smem + BIAS_OFF + tid * 4) = bv;
    }

    const uint32_t aAddrBase =
        (uint32_t)((wm * 64 + (lane & 15)) * LDS_ROW + ((lane >> 4) * 16));
    const uint32_t bAddrBase =
        (uint32_t)(A_STAGE +
                   (wn * 64 + (lane & 7) + ((lane >> 4) * 8)) * LDS_ROW +
                   (((lane >> 3) & 1) * 16));

    float acc[4][8][4];
#pragma unroll
    for (int mt = 0; mt < 4; ++mt)
#pragma unroll
        for (int nt = 0; nt < 8; ++nt)
#pragma unroll
            for (int i = 0; i < 4; ++i) acc[mt][nt][i] = 0.f;

    // prologue: fill stages 0..2 (chunks 0..2)
#pragma unroll
    for (int c = 0; c < 3; ++c)
        fill_full(sbase + c * STAGE_BYTES, Ag + (size_t)c * BKB,
                  Bg + (size_t)c * BKB, tid);

    uint32_t abuf[2][4][4], bbuf[2][8][2];

    const int NCHUNK = D_IN / BKE;   // 64
    for (int c = 0; c < NCHUNK; ++c) {
        asm volatile("cp.async.wait_group %0;" :: "n"(2));
        __syncthreads();

        const uint32_t stg = sbase + (c & 3) * STAGE_BYTES;
        const bool fill = (c + 3 < NCHUNK);
        const uint32_t fas = sbase + ((c + 3) & 3) * STAGE_BYTES;
        const char* agf = Ag + (size_t)(c + 3) * BKB;
        const char* bgf = Bg + (size_t)(c + 3) * BKB;

        load_frags(stg, aAddrBase, bAddrBase, 0, abuf[0], bbuf[0]);
#pragma unroll
        for (int ks = 0; ks < 4; ++ks) {
            const int cur = ks & 1;
            if (ks < 3)
                load_frags(stg, aAddrBase, bAddrBase, ks + 1,
                           abuf[1 - cur], bbuf[1 - cur]);
            if (fill) {   // 3 cp groups per ks, hidden under the 32 HMMAs below
                if (ks == 0) { cp_group<0>(fas, agf, bgf, tid);
                               cp_group<4>(fas, agf, bgf, tid);
                               cp_group<5>(fas, agf, bgf, tid); }
                if (ks == 1) { cp_group<1>(fas, agf, bgf, tid);
                               cp_group<6>(fas, agf, bgf, tid);
                               cp_group<7>(fas, agf, bgf, tid); }
                if (ks == 2) { cp_group<2>(fas, agf, bgf, tid);
                               cp_group<8>(fas, agf, bgf, tid);
                               cp_group<9>(fas, agf, bgf, tid); }
                if (ks == 3) { cp_group<3>(fas, agf, bgf, tid);
                               cp_group<10>(fas, agf, bgf, tid);
                               cp_group<11>(fas, agf, bgf, tid); }
            }
#pragma unroll
            for (int mt = 0; mt < 4; ++mt)
#pragma unroll
                for (int nt = 0; nt < 8; ++nt)
                    hmma16816(acc[mt][nt], abuf[cur][mt], bbuf[cur][nt]);
        }
        if (fill)
            asm volatile("cp.async.commit_group;" ::: "memory");
    }

    // epilogue: out = acc * (weight_scale * scale) + bias
    float am = __uint_as_float(g_absmax_u);
    float sc = __fdiv_rn(am, 127.0f);
    if (sc == 0.f) sc = 1.0f;
    float alpha = (*wscale) * sc;

    const float* bsh = reinterpret_cast<const float*>(smem + BIAS_OFF);
#pragma unroll
    for (int mt = 0; mt < 4; ++mt) {
#pragma unroll
        for (int nt = 0; nt < 8; ++nt) {
            int row = m0 + wm * 64 + mt * 16 + g;
            int lcol = wn * 64 + nt * 8 + t * 2;
            float b0 = bsh[lcol];
            float b1 = bsh[lcol + 1];
            float2 v0, v1;
            v0.x = acc[mt][nt][0] * alpha + b0;
            v0.y = acc[mt][nt][1] * alpha + b1;
            v1.x = acc[mt][nt][2] * alpha + b0;
            v1.y = acc[mt][nt][3] * alpha + b1;
            *reinterpret_cast<float2*>(out + (size_t)row * D_OUT + n0 + lcol) = v0;
            *reinterpret_cast<float2*>(out + (size_t)(row + 8) * D_OUT + n0 + lcol) = v1;
        }
    }
}

// ---------------- launcher --------------------------------------------------
extern "C" void kernel_launch(void* const* d_in, const int* in_sizes, int n_in,
                              void* d_out, int out_size) {
    const float* x    = (const float*)d_in[0];
    const int*   w    = (const int*)d_in[1];
    const float* ws   = (const float*)d_in[2];
    const float* bias = (const float*)d_in[3];
    float* out = (float*)d_out;

    cudaFuncSetAttribute(gemm_hmma, cudaFuncAttributeMaxDynamicSharedMemorySize,
                         SMEM_TOTAL);

    init_kernel<<<1, 1>>>();
    absmax_kernel<<<1024, 256>>>((const float4*)x, (N_TOK * D_IN) / 4);
    quant_kernel<<<2048, 256>>>((const float4*)x, (N_TOK * D_IN) / 4);
    wconv_kernel<<<1024, 256>>>((const int4*)w, (D_OUT * D_IN) / 4);

    dim3 grid(D_OUT / BN, N_TOK / BM);
    gemm_hmma<<<grid, NTHREADS, SMEM_TOTAL>>>(bias, ws, out);
}

// round 17
// speedup vs baseline: 1.7257x; 1.0731x over previous
// R16: rolling cross-chunk fragment prefetch (no per-chunk serial prime),
// 4-stage ring, wait_group 1 at chunk end. 256 thr, CTA 128x256, BKE=64.
#include <cuda_runtime.h>
#include <cuda_bf16.h>
#include <cstdint>
#include <cstddef>

#define N_TOK 8192
#define D_IN  4096
#define D_OUT 4096

__device__ __align__(16) __nv_bfloat16 g_Xb[(size_t)N_TOK * D_IN];   // 64 MB
__device__ __align__(16) __nv_bfloat16 g_Wb[(size_t)D_OUT * D_IN];   // 32 MB
__device__ unsigned g_absmax_u;

// ---------------- helpers ---------------------------------------------------
__device__ __forceinline__ uint32_t smem_u32(const void* p) {
    uint32_t a;
    asm("{ .reg .u64 t; cvta.to.shared.u64 t, %1; cvt.u32.u64 %0, t; }"
        : "=r"(a) : "l"(p));
    return a;
}

__device__ __forceinline__ void cp16(uint32_t dst, const void* src) {
    asm volatile("cp.async.cg.shared.global [%0], [%1], 16;" :: "r"(dst), "l"(src));
}

__device__ __forceinline__ void hmma16816(float* c, const uint32_t* a, const uint32_t* b) {
    asm volatile(
        "mma.sync.aligned.m16n8k16.row.col.f32.bf16.bf16.f32 "
        "{%0,%1,%2,%3}, {%4,%5,%6,%7}, {%8,%9}, {%0,%1,%2,%3};"
        : "+f"(c[0]), "+f"(c[1]), "+f"(c[2]), "+f"(c[3])
        : "r"(a[0]), "r"(a[1]), "r"(a[2]), "r"(a[3]), "r"(b[0]), "r"(b[1]));
}

__device__ __forceinline__ void ldm_x4(uint32_t* r, uint32_t addr) {
    asm volatile(
        "ldmatrix.sync.aligned.m8n8.x4.shared.b16 {%0,%1,%2,%3}, [%4];"
        : "=r"(r[0]), "=r"(r[1]), "=r"(r[2]), "=r"(r[3]) : "r"(addr));
}

// ---------------- pre-kernels ----------------------------------------------
__global__ void init_kernel() { g_absmax_u = 0u; }

__global__ void absmax_kernel(const float4* __restrict__ x, int n4) {
    float m = 0.f;
    for (int i = blockIdx.x * blockDim.x + threadIdx.x; i < n4;
         i += gridDim.x * blockDim.x) {
        float4 v = x[i];
        m = fmaxf(m, fmaxf(fmaxf(fabsf(v.x), fabsf(v.y)),
                           fmaxf(fabsf(v.z), fabsf(v.w))));
    }
#pragma unroll
    for (int o = 16; o > 0; o >>= 1)
        m = fmaxf(m, __shfl_xor_sync(0xffffffffu, m, o));
    __shared__ float red[8];
    if ((threadIdx.x & 31) == 0) red[threadIdx.x >> 5] = m;
    __syncthreads();
    if (threadIdx.x == 0) {
        float v = red[0];
#pragma unroll
        for (int i = 1; i < 8; ++i) v = fmaxf(v, red[i]);
        atomicMax(&g_absmax_u, __float_as_uint(v));   // values >= 0: bit-monotone
    }
}

__global__ void quant_kernel(const float4* __restrict__ x, int n4) {
    float am = __uint_as_float(g_absmax_u);
    float s = __fdiv_rn(am, 127.0f);            // exact IEEE div, matches reference
    if (s == 0.f) s = 1.0f;
    for (int i = blockIdx.x * blockDim.x + threadIdx.x; i < n4;
         i += gridDim.x * blockDim.x) {
        float4 v = x[i];
        float a0 = fminf(fmaxf(rintf(__fdiv_rn(v.x, s)), -128.f), 127.f);
        float a1 = fminf(fmaxf(rintf(__fdiv_rn(v.y, s)), -128.f), 127.f);
        float a2 = fminf(fmaxf(rintf(__fdiv_rn(v.z, s)), -128.f), 127.f);
        float a3 = fminf(fmaxf(rintf(__fdiv_rn(v.w, s)), -128.f), 127.f);
        __nv_bfloat162 h0 = __floats2bfloat162_rn(a0, a1);
        __nv_bfloat162 h1 = __floats2bfloat162_rn(a2, a3);
        uint2 u;
        u.x = *reinterpret_cast<uint32_t*>(&h0);
        u.y = *reinterpret_cast<uint32_t*>(&h1);
        reinterpret_cast<uint2*>(g_Xb)[i] = u;
    }
}

__global__ void wconv_kernel(const int4* __restrict__ w, int n4) {
    for (int i = blockIdx.x * blockDim.x + threadIdx.x; i < n4;
         i += gridDim.x * blockDim.x) {
        int4 v = w[i];   // values in {-1, 0, 1}
        __nv_bfloat162 h0 = __floats2bfloat162_rn((float)v.x, (float)v.y);
        __nv_bfloat162 h1 = __floats2bfloat162_rn((float)v.z, (float)v.w);
        uint2 u;
        u.x = *reinterpret_cast<uint32_t*>(&h0);
        u.y = *reinterpret_cast<uint32_t*>(&h1);
        reinterpret_cast<uint2*>(g_Wb)[i] = u;
    }
}

// ---------------- bf16 GEMM: C[8192,4096] = Xb @ Wb^T -----------------------
#define BM 128
#define BN 256
#define BKE 64
#define BKB (BKE * 2)                     // 128 bytes per row per chunk
#define LDS_ROW 144                       // 128B data + 16B pad
#define A_STAGE (BM * LDS_ROW)            // 18432
#define B_STAGE (BN * LDS_ROW)            // 36864
#define STAGE_BYTES (A_STAGE + B_STAGE)   // 55296
#define STAGES 4
#define BIAS_OFF (STAGES * STAGE_BYTES)   // 221184
#define SMEM_TOTAL (BIAS_OFF + BN * 4)    // 222208
#define NTHREADS 256

// one cp.async group: 256 ops, 1/thread. G in [0,12): G<4 -> A, else B.
template <int G>
__device__ __forceinline__ void cp_group(uint32_t fas, const char* agf,
                                         const char* bgf, int tid) {
    if (G < 4) {
        int idx = G * NTHREADS + tid;            // 0..1023 -> A
        int row = idx >> 3, cc = idx & 7;
        cp16(fas + row * LDS_ROW + cc * 16,
             agf + (size_t)row * (D_IN * 2) + cc * 16);
    } else {
        int j = (G - 4) * NTHREADS + tid;        // 0..2047 -> B
        int row = j >> 3, cc = j & 7;
        cp16(fas + A_STAGE + row * LDS_ROW + cc * 16,
             bgf + (size_t)row * (D_IN * 2) + cc * 16);
    }
}

__device__ __forceinline__ void fill_full(uint32_t fas, const char* agf,
                                          const char* bgf, int tid) {
    cp_group<0>(fas, agf, bgf, tid);  cp_group<1>(fas, agf, bgf, tid);
    cp_group<2>(fas, agf, bgf, tid);  cp_group<3>(fas, agf, bgf, tid);
    cp_group<4>(fas, agf, bgf, tid);  cp_group<5>(fas, agf, bgf, tid);
    cp_group<6>(fas, agf, bgf, tid);  cp_group<7>(fas, agf, bgf, tid);
    cp_group<8>(fas, agf, bgf, tid);  cp_group<9>(fas, agf, bgf, tid);
    cp_group<10>(fas, agf, bgf, tid); cp_group<11>(fas, agf, bgf, tid);
    asm volatile("cp.async.commit_group;" ::: "memory");
}

__device__ __forceinline__ void load_frags(uint32_t stg, uint32_t aAddrBase,
                                           uint32_t bAddrBase, int ks,
                                           uint32_t a[4][4], uint32_t b[8][2]) {
#pragma unroll
    for (int mt = 0; mt < 4; ++mt)
        ldm_x4(a[mt], stg + aAddrBase + mt * (16 * LDS_ROW) + ks * 32);
#pragma unroll
    for (int ntp = 0; ntp < 4; ++ntp) {
        uint32_t r[4];
        ldm_x4(r, stg + bAddrBase + ntp * (16 * LDS_ROW) + ks * 32);
        b[ntp * 2 + 0][0] = r[0];
        b[ntp * 2 + 0][1] = r[1];
        b[ntp * 2 + 1][0] = r[2];
        b[ntp * 2 + 1][1] = r[3];
    }
}

__global__ void __launch_bounds__(NTHREADS, 1)
gemm_hmma(const float* __restrict__ bias, const float* __restrict__ wscale,
          float* __restrict__ out) {
    extern __shared__ char smem[];
    const uint32_t sbase = smem_u32(smem);
    const int tid = threadIdx.x;
    const int wid = tid >> 5, lane = tid & 31;
    const int g = lane >> 2, t = lane & 3;
    const int wm = wid & 1, wn = wid >> 1;           // 2 warps in M, 4 in N
    const int m0 = blockIdx.y * BM, n0 = blockIdx.x * BN;

    const char* Ag = (const char*)g_Xb + (size_t)m0 * (D_IN * 2);
    const char* Bg = (const char*)g_Wb + (size_t)n0 * (D_IN * 2);

    if (tid < BN) {
        float bv = bias[n0 + tid];
        *reinterpret_cast<float*>(smem + BIAS_OFF + tid * 4) = bv;
    }

    const uint32_t aAddrBase =
        (uint32_t)((wm * 64 + (lane & 15)) * LDS_ROW + ((lane >> 4) * 16));
    const uint32_t bAddrBase =
        (uint32_t)(A_STAGE +
                   (wn * 64 + (lane & 7) + ((lane >> 4) * 8)) * LDS_ROW +
                   (((lane >> 3) & 1) * 16));

    float acc[4][8][4];
#pragma unroll
    for (int mt = 0; mt < 4; ++mt)
#pragma unroll
        for (int nt = 0; nt < 8; ++nt)
#pragma unroll
            for (int i = 0; i < 4; ++i) acc[mt][nt][i] = 0.f;

    // prologue: fill stages 0..2 (chunks 0..2), then prime chunk0/ks0 frags
#pragma unroll
    for (int c = 0; c < 3; ++c)
        fill_full(sbase + c * STAGE_BYTES, Ag + (size_t)c * BKB,
                  Bg + (size_t)c * BKB, tid);
    asm volatile("cp.async.wait_group %0;" :: "n"(2));
    __syncthreads();

    uint32_t abuf[2][4][4], bbuf[2][8][2];
    load_frags(sbase, aAddrBase, bAddrBase, 0, abuf[0], bbuf[0]);

    const int NCHUNK = D_IN / BKE;   // 64
    for (int c = 0; c < NCHUNK; ++c) {
        const uint32_t stg = sbase + (c & 3) * STAGE_BYTES;
        const uint32_t stg_next = sbase + ((c + 1) & 3) * STAGE_BYTES;
        const bool have_next = (c + 1 < NCHUNK);
        const bool fill = (c + 3 < NCHUNK);
        const uint32_t fas = sbase + ((c + 3) & 3) * STAGE_BYTES;
        const char* agf = Ag + (size_t)(c + 3) * BKB;
        const char* bgf = Bg + (size_t)(c + 3) * BKB;

#pragma unroll
        for (int ks = 0; ks < 4; ++ks) {
            const int cur = ks & 1;
            if (ks < 3) {
                load_frags(stg, aAddrBase, bAddrBase, ks + 1,
                           abuf[1 - cur], bbuf[1 - cur]);
            } else if (have_next) {
                // rolling prefetch: chunk c+1 / ks0 from stage (c+1)&3.
                // Safe: stage confirmed complete+visible by wait+sync at end
                // of chunk c-1; no concurrent writes target it (fills go to
                // stages c+3 / c+4).
                load_frags(stg_next, aAddrBase, bAddrBase, 0,
                           abuf[1 - cur], bbuf[1 - cur]);
            }
            if (fill) {   // 3 cp groups per ks, hidden under the 32 HMMAs below
                if (ks == 0) { cp_group<0>(fas, agf, bgf, tid);
                               cp_group<4>(fas, agf, bgf, tid);
                               cp_group<5>(fas, agf, bgf, tid); }
                if (ks == 1) { cp_group<1>(fas, agf, bgf, tid);
                               cp_group<6>(fas, agf, bgf, tid);
                               cp_group<7>(fas, agf, bgf, tid); }
                if (ks == 2) { cp_group<2>(fas, agf, bgf, tid);
                               cp_group<8>(fas, agf, bgf, tid);
                               cp_group<9>(fas, agf, bgf, tid); }
                if (ks == 3) { cp_group<3>(fas, agf, bgf, tid);
                               cp_group<10>(fas, agf, bgf, tid);
                               cp_group<11>(fas, agf, bgf, tid); }
            }
#pragma unroll
            for (int mt = 0; mt < 4; ++mt)
#pragma unroll
                for (int nt = 0; nt < 8; ++nt)
                    hmma16816(acc[mt][nt], abuf[cur][mt], bbuf[cur][nt]);
        }
        if (fill)
            asm volatile("cp.async.commit_group;" ::: "memory");
        // guarantees stages c+1 (body) and c+2 (ks3 rolling prefetch) for the
        // next chunk; ~1 full chunk of slack on the newest outstanding group.
        asm volatile("cp.async.wait_group %0;" :: "n"(1));
        __syncthreads();
    }

    // epilogue: out = acc * (weight_scale * scale) + bias
    float am = __uint_as_float(g_absmax_u);
    float sc = __fdiv_rn(am, 127.0f);
    if (sc == 0.f) sc = 1.0f;
    float alpha = (*wscale) * sc;

    const float* bsh = reinterpret_cast<const float*>(smem + BIAS_OFF);
#pragma unroll
    for (int mt = 0; mt < 4; ++mt) {
#pragma unroll
        for (int nt = 0; nt < 8; ++nt) {
            int row = m0 + wm * 64 + mt * 16 + g;
            int lcol = wn * 64 + nt * 8 + t * 2;
            float b0 = bsh[lcol];
            float b1 = bsh[lcol + 1];
            float2 v0, v1;
            v0.x = acc[mt][nt][0] * alpha + b0;
            v0.y = acc[mt][nt][1] * alpha + b1;
            v1.x = acc[mt][nt][2] * alpha + b0;
            v1.y = acc[mt][nt][3] * alpha + b1;
            *reinterpret_cast<float2*>(out + (size_t)row * D_OUT + n0 + lcol) = v0;
            *reinterpret_cast<float2*>(out + (size_t)(row + 8) * D_OUT + n0 + lcol) = v1;
        }
    }
}

// ---------------- launcher --------------------------------------------------
extern "C" void kernel_launch(void* const* d_in, const int* in_sizes, int n_in,
                              void* d_out, int out_size) {
    const float* x    = (const float*)d_in[0];
    const int*   w    = (const int*)d_in[1];
    const float* ws   = (const float*)d_in[2];
    const float* bias = (const float*)d_in[3];
    float* out = (float*)d_out;

    cudaFuncSetAttribute(gemm_hmma, cudaFuncAttributeMaxDynamicSharedMemorySize,
                         SMEM_TOTAL);

    init_kernel<<<1, 1>>>();
    absmax_kernel<<<2048, 256>>>((const float4*)x, (N_TOK * D_IN) / 4);
    quant_kernel<<<4096, 256>>>((const float4*)x, (N_TOK * D_IN) / 4);
    wconv_kernel<<<2048, 256>>>((const int4*)w, (D_OUT * D_IN) / 4);

    dim3 grid(D_OUT / BN, N_TOK / BM);
    gemm_hmma<<<grid, NTHREADS, SMEM_TOTAL>>>(bias, ws, out);
}